// round 2
// baseline (speedup 1.0000x reference)
#include <cuda_runtime.h>
#include <math.h>

#define N_NODES 50000
#define N_EDGES 400000
#define N_EDGES_SL (N_EDGES + N_NODES)
#define NEG_SLOPE 0.2f

// ---------------- scratch (device globals; no allocation allowed) ------------
static __device__ float g_h[(size_t)N_NODES * 512];      // pre-aggregation features
static __device__ float g_feat[(size_t)N_NODES * 512];   // layer1 out / layer3 out
static __device__ float g_feat2[(size_t)N_NODES * 128];  // layer2 out
static __device__ float g_s[N_NODES * 4];
static __device__ float g_d[N_NODES * 4];
static __device__ int   g_cnt[N_NODES];                  // degree counts / fill cursors
static __device__ int   g_rowptr[N_NODES + 1];
static __device__ int   g_csrsrc[N_EDGES_SL];

// ---------------- CSR build --------------------------------------------------
__global__ void k_setone(int* cnt, int n) {
    int i = blockIdx.x * blockDim.x + threadIdx.x;
    if (i < n) cnt[i] = 1;  // self-loop pre-counted
}

__global__ void k_count(const int* __restrict__ dst, int* cnt, int e) {
    int i = blockIdx.x * blockDim.x + threadIdx.x;
    if (i < e) atomicAdd(&cnt[dst[i]], 1);
}

// single-block exclusive scan of cnt[0..n) -> rowptr; also zeroes cnt for reuse
__global__ void k_scan(int* cnt, int* rowptr, int n) {
    __shared__ int temp[1024];
    __shared__ int carry;
    if (threadIdx.x == 0) carry = 0;
    __syncthreads();
    for (int base = 0; base < n; base += 1024) {
        int i = base + threadIdx.x;
        int v = (i < n) ? cnt[i] : 0;
        temp[threadIdx.x] = v;
        __syncthreads();
        #pragma unroll
        for (int off = 1; off < 1024; off <<= 1) {
            int t = (threadIdx.x >= off) ? temp[threadIdx.x - off] : 0;
            __syncthreads();
            temp[threadIdx.x] += t;
            __syncthreads();
        }
        if (i < n) {
            rowptr[i] = carry + temp[threadIdx.x] - v;  // exclusive
            cnt[i] = 0;                                  // reset fill cursor
        }
        __syncthreads();
        if (threadIdx.x == 0) carry += temp[1023];
        __syncthreads();
    }
    if (threadIdx.x == 0) rowptr[n] = carry;
}

__global__ void k_scatter(const int* __restrict__ src, const int* __restrict__ dst,
                          const int* __restrict__ rowptr, int* fill, int* csrsrc,
                          int e, int n) {
    int i = blockIdx.x * blockDim.x + threadIdx.x;
    if (i < e) {
        int d = dst[i];
        int pos = atomicAdd(&fill[d], 1);
        csrsrc[rowptr[d] + pos] = src[i];
    } else if (i < e + n) {
        int node = i - e;
        int pos = atomicAdd(&fill[node], 1);
        csrsrc[rowptr[node] + pos] = node;  // self loop
    }
}

// ---------------- SGEMM: C[N,M] = A[N,K] * B[M,K]^T --------------------------
#define BM 64
#define BN 64
#define BKK 16
__global__ __launch_bounds__(256) void k_sgemm(int N, int M, int K,
                                               const float* __restrict__ A,
                                               const float* __restrict__ B,
                                               float* __restrict__ C) {
    __shared__ __align__(16) float As[BKK][BM];
    __shared__ __align__(16) float Bs[BKK][BN];
    int tid = threadIdx.x;
    int tx = tid & 15, ty = tid >> 4;
    int row0 = blockIdx.y * BM, col0 = blockIdx.x * BN;
    int lr = tid >> 2, lc = tid & 3;  // 64 rows x 4 float4-groups
    float acc[4][4] = {};
    for (int k0 = 0; k0 < K; k0 += BKK) {
        float4 av;
        int ar = row0 + lr;
        if (ar < N) av = *(const float4*)(A + (size_t)ar * K + k0 + lc * 4);
        else        av = make_float4(0.f, 0.f, 0.f, 0.f);
        As[lc * 4 + 0][lr] = av.x; As[lc * 4 + 1][lr] = av.y;
        As[lc * 4 + 2][lr] = av.z; As[lc * 4 + 3][lr] = av.w;
        float4 bv = *(const float4*)(B + (size_t)(col0 + lr) * K + k0 + lc * 4);
        Bs[lc * 4 + 0][lr] = bv.x; Bs[lc * 4 + 1][lr] = bv.y;
        Bs[lc * 4 + 2][lr] = bv.z; Bs[lc * 4 + 3][lr] = bv.w;
        __syncthreads();
        #pragma unroll
        for (int kk = 0; kk < BKK; kk++) {
            float4 a4 = *(const float4*)&As[kk][ty * 4];
            float4 b4 = *(const float4*)&Bs[kk][tx * 4];
            float a[4] = {a4.x, a4.y, a4.z, a4.w};
            float b[4] = {b4.x, b4.y, b4.z, b4.w};
            #pragma unroll
            for (int i = 0; i < 4; i++)
                #pragma unroll
                for (int j = 0; j < 4; j++)
                    acc[i][j] += a[i] * b[j];
        }
        __syncthreads();
    }
    #pragma unroll
    for (int i = 0; i < 4; i++) {
        int r = row0 + ty * 4 + i;
        if (r < N) {
            float4 o = make_float4(acc[i][0], acc[i][1], acc[i][2], acc[i][3]);
            *(float4*)(C + (size_t)r * M + col0 + tx * 4) = o;
        }
    }
}

// ---------------- tiny GEMM for layer 3 (M=8, K=128) -------------------------
__global__ void k_gemm8(const float* __restrict__ X, const float* __restrict__ W,
                        float* __restrict__ Hout, int n) {
    __shared__ float Ws[8 * 128];
    for (int i = threadIdx.x; i < 1024; i += blockDim.x) Ws[i] = W[i];
    __syncthreads();
    int node = blockIdx.x * blockDim.x + threadIdx.x;
    if (node >= n) return;
    float acc[8] = {};
    const float4* xr = (const float4*)(X + (size_t)node * 128);
    #pragma unroll 8
    for (int k4 = 0; k4 < 32; k4++) {
        float4 xv = xr[k4];
        #pragma unroll
        for (int m = 0; m < 8; m++) {
            const float* w = &Ws[m * 128 + k4 * 4];
            acc[m] += xv.x * w[0] + xv.y * w[1] + xv.z * w[2] + xv.w * w[3];
        }
    }
    #pragma unroll
    for (int m = 0; m < 8; m++) Hout[(size_t)node * 8 + m] = acc[m];
}

// ---------------- per-node attention projections s,d -------------------------
template <int H, int C>
__global__ void k_sd(const float* __restrict__ h, const float* __restrict__ as_,
                     const float* __restrict__ ad_, float* __restrict__ s,
                     float* __restrict__ d, int n) {
    int gt = blockIdx.x * blockDim.x + threadIdx.x;
    int warp = gt >> 5, lane = gt & 31;
    if (warp >= n * H) return;
    int node = warp / H, hh = warp % H;
    const float* row = h + (size_t)node * H * C + hh * C;
    float ss = 0.f, dd = 0.f;
    for (int c = lane; c < C; c += 32) {
        float v = row[c];
        ss += v * as_[hh * C + c];
        dd += v * ad_[hh * C + c];
    }
    #pragma unroll
    for (int o = 16; o; o >>= 1) {
        ss += __shfl_xor_sync(0xffffffffu, ss, o);
        dd += __shfl_xor_sync(0xffffffffu, dd, o);
    }
    if (lane == 0) { s[warp] = ss; d[warp] = dd; }
}

// ---------------- GAT aggregation: one block per dst node --------------------
// softmax over incoming edges, weighted sum of h[src], + bias, elu
template <int H, int C>
__global__ void k_gat_agg(const float* __restrict__ h, const float* __restrict__ s,
                          const float* __restrict__ dvals, const float* __restrict__ bias,
                          const int* __restrict__ rowptr, const int* __restrict__ csrsrc,
                          float* __restrict__ out) {
    constexpr int HC = H * C;
    int node = blockIdx.x;
    int tid = threadIdx.x;
    __shared__ float dv[H], mx[H], den[H];
    __shared__ int ssrc[32];
    __shared__ float wch[32 * H];
    int st = rowptr[node], en = rowptr[node + 1];
    if (tid < H) dv[tid] = dvals[node * H + tid];
    __syncthreads();
    if (tid < H) {
        float dvv = dv[tid];
        float m = -1e30f;
        for (int j = st; j < en; j++) {
            float e = s[csrsrc[j] * H + tid] + dvv;
            e = e > 0.f ? e : NEG_SLOPE * e;
            m = fmaxf(m, e);
        }
        float dn = 0.f;
        for (int j = st; j < en; j++) {
            float e = s[csrsrc[j] * H + tid] + dvv;
            e = e > 0.f ? e : NEG_SLOPE * e;
            dn += expf(e - m);
        }
        mx[tid] = m; den[tid] = dn;
    }
    float acc = 0.f;
    int head = tid / C;
    for (int base = st; base < en; base += 32) {
        int len = min(32, en - base);
        __syncthreads();  // protects ssrc/wch from previous chunk's readers, mx/den visibility
        if (tid < len) ssrc[tid] = csrsrc[base + tid];
        __syncthreads();
        if (tid < len * H) {
            int j = tid / H, hh = tid - j * H;
            float e = s[ssrc[j] * H + hh] + dv[hh];
            e = e > 0.f ? e : NEG_SLOPE * e;
            wch[j * H + hh] = expf(e - mx[hh]);
        }
        __syncthreads();
        for (int j = 0; j < len; j++)
            acc += wch[j * H + head] * h[(size_t)ssrc[j] * HC + tid];
    }
    float r = acc / den[head] + bias[tid];
    out[(size_t)node * HC + tid] = r > 0.f ? r : expm1f(r);
}

// ---------------- layer-3 aggregation (H=1, C=8): thread per node ------------
__global__ void k_gat_agg8(const float* __restrict__ h, const float* __restrict__ s,
                           const float* __restrict__ dvals, const float* __restrict__ bias,
                           const int* __restrict__ rowptr, const int* __restrict__ csrsrc,
                           float* __restrict__ out, int n) {
    int node = blockIdx.x * blockDim.x + threadIdx.x;
    if (node >= n) return;
    int st = rowptr[node], en = rowptr[node + 1];
    float dvv = dvals[node];
    float m = -1e30f;
    for (int j = st; j < en; j++) {
        float e = s[csrsrc[j]] + dvv;
        e = e > 0.f ? e : NEG_SLOPE * e;
        m = fmaxf(m, e);
    }
    float den = 0.f;
    float acc[8] = {};
    for (int j = st; j < en; j++) {
        int src = csrsrc[j];
        float e = s[src] + dvv;
        e = e > 0.f ? e : NEG_SLOPE * e;
        float w = expf(e - m);
        den += w;
        const float4* hp = (const float4*)(h + (size_t)src * 8);
        float4 v0 = hp[0], v1 = hp[1];
        acc[0] += w * v0.x; acc[1] += w * v0.y; acc[2] += w * v0.z; acc[3] += w * v0.w;
        acc[4] += w * v1.x; acc[5] += w * v1.y; acc[6] += w * v1.z; acc[7] += w * v1.w;
    }
    float inv = 1.f / den;
    #pragma unroll
    for (int c = 0; c < 8; c++) {
        float r = acc[c] * inv + bias[c];
        out[(size_t)node * 8 + c] = r > 0.f ? r : expm1f(r);
    }
}

// ---------------- final edge MLP ---------------------------------------------
__global__ void k_edge_mlp(const float* __restrict__ h, const int* __restrict__ src,
                           const int* __restrict__ dst, const float* __restrict__ ea,
                           const float* __restrict__ yr, const float* __restrict__ qt,
                           const float* __restrict__ w1, const float* __restrict__ b1,
                           const float* __restrict__ w2, const float* __restrict__ b2,
                           float* __restrict__ out, int e) {
    __shared__ float W1s[16 * 19];
    __shared__ float B1s[16];
    __shared__ float W2s[16];
    __shared__ float B2s;
    int tid = threadIdx.x;
    for (int i = tid; i < 304; i += blockDim.x) W1s[i] = w1[i];
    if (tid < 16) { B1s[tid] = b1[tid]; W2s[tid] = w2[tid]; }
    if (tid == 0) B2s = b2[0];
    __syncthreads();
    int i = blockIdx.x * blockDim.x + tid;
    if (i >= e) return;
    float z[19];
    int ss = src[i], dd = dst[i];
    const float4* hs = (const float4*)(h + (size_t)ss * 8);
    const float4* hd = (const float4*)(h + (size_t)dd * 8);
    float4 a0 = hs[0], a1 = hs[1], c0 = hd[0], c1 = hd[1];
    z[0] = a0.x; z[1] = a0.y; z[2] = a0.z; z[3] = a0.w;
    z[4] = a1.x; z[5] = a1.y; z[6] = a1.z; z[7] = a1.w;
    z[8] = c0.x; z[9] = c0.y; z[10] = c0.z; z[11] = c0.w;
    z[12] = c1.x; z[13] = c1.y; z[14] = c1.z; z[15] = c1.w;
    z[16] = ea[i]; z[17] = yr[i]; z[18] = qt[i];
    float o = B2s;
    #pragma unroll
    for (int r = 0; r < 16; r++) {
        float a = B1s[r];
        #pragma unroll
        for (int c = 0; c < 19; c++) a += W1s[r * 19 + c] * z[c];
        o += W2s[r] * fmaxf(a, 0.f);
    }
    out[i] = o;
}

// ---------------- launch -----------------------------------------------------
extern "C" void kernel_launch(void* const* d_in, const int* in_sizes, int n_in,
                              void* d_out, int out_size) {
    const float* x    = (const float*)d_in[0];
    const int*   ei   = (const int*)d_in[1];
    const float* ea   = (const float*)d_in[2];
    const float* yr   = (const float*)d_in[3];
    const float* qt   = (const float*)d_in[4];
    const float* W1   = (const float*)d_in[5];
    const float* a1s  = (const float*)d_in[6];
    const float* a1d  = (const float*)d_in[7];
    const float* b1   = (const float*)d_in[8];
    const float* W2   = (const float*)d_in[9];
    const float* a2s  = (const float*)d_in[10];
    const float* a2d  = (const float*)d_in[11];
    const float* b2   = (const float*)d_in[12];
    const float* W3   = (const float*)d_in[13];
    const float* a3s  = (const float*)d_in[14];
    const float* a3d  = (const float*)d_in[15];
    const float* b3   = (const float*)d_in[16];
    const float* fc1w = (const float*)d_in[17];
    const float* fc1b = (const float*)d_in[18];
    const float* fc2w = (const float*)d_in[19];
    const float* fc2b = (const float*)d_in[20];
    const int* srcp = ei;
    const int* dstp = ei + N_EDGES;
    float* out = (float*)d_out;

    float *h, *feat, *feat2, *sarr, *darr;
    int *cnt, *rowptr, *csrsrc;
    cudaGetSymbolAddress((void**)&h,      g_h);
    cudaGetSymbolAddress((void**)&feat,   g_feat);
    cudaGetSymbolAddress((void**)&feat2,  g_feat2);
    cudaGetSymbolAddress((void**)&sarr,   g_s);
    cudaGetSymbolAddress((void**)&darr,   g_d);
    cudaGetSymbolAddress((void**)&cnt,    g_cnt);
    cudaGetSymbolAddress((void**)&rowptr, g_rowptr);
    cudaGetSymbolAddress((void**)&csrsrc, g_csrsrc);

    const int N = N_NODES, E = N_EDGES;

    // CSR build (by destination, self-loops included)
    k_setone<<<(N + 255) / 256, 256>>>(cnt, N);
    k_count<<<(E + 255) / 256, 256>>>(dstp, cnt, E);
    k_scan<<<1, 1024>>>(cnt, rowptr, N);
    k_scatter<<<(E + N + 255) / 256, 256>>>(srcp, dstp, rowptr, cnt, csrsrc, E, N);

    // Layer 1: 128 -> 4x128
    {
        dim3 grid(512 / BN, (N + BM - 1) / BM);
        k_sgemm<<<grid, 256>>>(N, 512, 128, x, W1, h);
        int warps = N * 4;
        k_sd<4, 128><<<(warps * 32 + 255) / 256, 256>>>(h, a1s, a1d, sarr, darr, N);
        k_gat_agg<4, 128><<<N, 512>>>(h, sarr, darr, b1, rowptr, csrsrc, feat);
    }
    // Layer 2: 512 -> 4x32
    {
        dim3 grid(128 / BN, (N + BM - 1) / BM);
        k_sgemm<<<grid, 256>>>(N, 128, 512, feat, W2, h);
        int warps = N * 4;
        k_sd<4, 32><<<(warps * 32 + 255) / 256, 256>>>(h, a2s, a2d, sarr, darr, N);
        k_gat_agg<4, 32><<<N, 128>>>(h, sarr, darr, b2, rowptr, csrsrc, feat2);
    }
    // Layer 3: 128 -> 1x8
    {
        k_gemm8<<<(N + 255) / 256, 256>>>(feat2, W3, h, N);
        int warps = N * 1;
        k_sd<1, 8><<<(warps * 32 + 255) / 256, 256>>>(h, a3s, a3d, sarr, darr, N);
        k_gat_agg8<<<(N + 255) / 256, 256>>>(h, sarr, darr, b3, rowptr, csrsrc, feat, N);
    }
    // Edge MLP
    k_edge_mlp<<<(E + 255) / 256, 256>>>(feat, srcp, dstp, ea, yr, qt,
                                         fc1w, fc1b, fc2w, fc2b, out, E);
}

// round 4
// speedup vs baseline: 1.1420x; 1.1420x over previous
#include <cuda_runtime.h>
#include <math.h>

#define N_NODES 50000
#define N_EDGES 400000
#define N_EDGES_SL (N_EDGES + N_NODES)
#define NEG_SLOPE 0.2f

// ---------------- scratch (device globals; no allocation allowed) ------------
static __device__ float g_h[(size_t)N_NODES * 512];      // pre-aggregation features
static __device__ float g_feat[(size_t)N_NODES * 512];   // layer1 out / layer3 out
static __device__ float g_feat2[(size_t)N_NODES * 128];  // layer2 out
static __device__ float g_s[N_NODES * 4];
static __device__ float g_d[N_NODES * 4];
static __device__ int   g_cnt[N_NODES];                  // degree counts / fill cursors
static __device__ int   g_rowptr[N_NODES + 1];
static __device__ int   g_csrsrc[N_EDGES_SL];
static __device__ int   g_part[64];                      // scan partials

// ---------------- CSR build --------------------------------------------------
__global__ void k_setone(int* cnt, int n) {
    int i = blockIdx.x * blockDim.x + threadIdx.x;
    if (i < n) cnt[i] = 1;  // self-loop pre-counted
}

__global__ void k_count(const int* __restrict__ dst, int* cnt, int e) {
    int i = blockIdx.x * blockDim.x + threadIdx.x;
    if (i < e) atomicAdd(&cnt[dst[i]], 1);
}

// hierarchical scan: per-block 1024-wide scan -> partials
__global__ void k_blockscan(const int* __restrict__ cnt, int* rowptr, int* partials, int n) {
    __shared__ int temp[1024];
    int i = blockIdx.x * 1024 + threadIdx.x;
    int v = (i < n) ? cnt[i] : 0;
    temp[threadIdx.x] = v;
    __syncthreads();
    #pragma unroll
    for (int off = 1; off < 1024; off <<= 1) {
        int t = (threadIdx.x >= off) ? temp[threadIdx.x - off] : 0;
        __syncthreads();
        temp[threadIdx.x] += t;
        __syncthreads();
    }
    if (i < n) rowptr[i] = temp[threadIdx.x] - v;  // exclusive within block
    if (threadIdx.x == 1023) partials[blockIdx.x] = temp[1023];
}

__global__ void k_scanpartials(int* partials, int* rowptr, int nb, int n) {
    __shared__ int t[64];
    int tid = threadIdx.x;
    int v = (tid < nb) ? partials[tid] : 0;
    t[tid] = v;
    __syncthreads();
    #pragma unroll
    for (int off = 1; off < 64; off <<= 1) {
        int u = (tid >= off) ? t[tid - off] : 0;
        __syncthreads();
        t[tid] += u;
        __syncthreads();
    }
    if (tid < nb) partials[tid] = t[tid] - v;  // exclusive
    if (tid == 63) rowptr[n] = t[63];          // total
}

__global__ void k_addoff(int* rowptr, const int* __restrict__ partials, int* cnt, int n) {
    int i = blockIdx.x * blockDim.x + threadIdx.x;
    if (i < n) { rowptr[i] += partials[i >> 10]; cnt[i] = 0; }
}

__global__ void k_scatter(const int* __restrict__ src, const int* __restrict__ dst,
                          const int* __restrict__ rowptr, int* fill, int* csrsrc,
                          int e, int n) {
    int i = blockIdx.x * blockDim.x + threadIdx.x;
    if (i < e) {
        int d = dst[i];
        int pos = atomicAdd(&fill[d], 1);
        csrsrc[rowptr[d] + pos] = src[i];
    } else if (i < e + n) {
        int node = i - e;
        int pos = atomicAdd(&fill[node], 1);
        csrsrc[rowptr[node] + pos] = node;  // self loop
    }
}

// ---------------- SGEMM: C[N,M] = A[N,K] * B[M,K]^T  (128x128x8, 8x8 micro) --
#define TBM 128
#define TBN 128
#define TBK 8
__global__ __launch_bounds__(256) void k_sgemm(int N, int M, int K,
                                               const float* __restrict__ A,
                                               const float* __restrict__ B,
                                               float* __restrict__ C) {
    __shared__ __align__(16) float As[TBK][TBM];
    __shared__ __align__(16) float Bs[TBK][TBN];
    int tid = threadIdx.x;
    int tx = tid & 15, ty = tid >> 4;           // 16x16 thread grid
    int row0 = blockIdx.y * TBM, col0 = blockIdx.x * TBN;
    int lr = tid >> 1;                           // 0..127
    int lk = (tid & 1) * 4;                      // 0 or 4
    float acc[8][8] = {};
    for (int k0 = 0; k0 < K; k0 += TBK) {
        float4 av = make_float4(0.f, 0.f, 0.f, 0.f);
        int ar = row0 + lr;
        if (ar < N) av = *(const float4*)(A + (size_t)ar * K + k0 + lk);
        As[lk + 0][lr] = av.x; As[lk + 1][lr] = av.y;
        As[lk + 2][lr] = av.z; As[lk + 3][lr] = av.w;
        float4 bv = *(const float4*)(B + (size_t)(col0 + lr) * K + k0 + lk);
        Bs[lk + 0][lr] = bv.x; Bs[lk + 1][lr] = bv.y;
        Bs[lk + 2][lr] = bv.z; Bs[lk + 3][lr] = bv.w;
        __syncthreads();
        #pragma unroll
        for (int kk = 0; kk < TBK; kk++) {
            float a[8], b[8];
            *(float4*)&a[0] = *(const float4*)&As[kk][ty * 8];
            *(float4*)&a[4] = *(const float4*)&As[kk][ty * 8 + 4];
            *(float4*)&b[0] = *(const float4*)&Bs[kk][tx * 8];
            *(float4*)&b[4] = *(const float4*)&Bs[kk][tx * 8 + 4];
            #pragma unroll
            for (int i = 0; i < 8; i++)
                #pragma unroll
                for (int j = 0; j < 8; j++)
                    acc[i][j] += a[i] * b[j];
        }
        __syncthreads();
    }
    #pragma unroll
    for (int i = 0; i < 8; i++) {
        int r = row0 + ty * 8 + i;
        if (r < N) {
            float* cp = C + (size_t)r * M + col0 + tx * 8;
            *(float4*)cp       = make_float4(acc[i][0], acc[i][1], acc[i][2], acc[i][3]);
            *(float4*)(cp + 4) = make_float4(acc[i][4], acc[i][5], acc[i][6], acc[i][7]);
        }
    }
}

// ---------------- tiny GEMM for layer 3 (M=8, K=128) -------------------------
__global__ void k_gemm8(const float* __restrict__ X, const float* __restrict__ W,
                        float* __restrict__ Hout, int n) {
    __shared__ float Ws[8 * 128];
    for (int i = threadIdx.x; i < 1024; i += blockDim.x) Ws[i] = W[i];
    __syncthreads();
    int node = blockIdx.x * blockDim.x + threadIdx.x;
    if (node >= n) return;
    float acc[8] = {};
    const float4* xr = (const float4*)(X + (size_t)node * 128);
    #pragma unroll 8
    for (int k4 = 0; k4 < 32; k4++) {
        float4 xv = xr[k4];
        #pragma unroll
        for (int m = 0; m < 8; m++) {
            const float* w = &Ws[m * 128 + k4 * 4];
            acc[m] += xv.x * w[0] + xv.y * w[1] + xv.z * w[2] + xv.w * w[3];
        }
    }
    #pragma unroll
    for (int m = 0; m < 8; m++) Hout[(size_t)node * 8 + m] = acc[m];
}

// ---------------- per-node attention projections s,d -------------------------
template <int H, int C>
__global__ void k_sd(const float* __restrict__ h, const float* __restrict__ as_,
                     const float* __restrict__ ad_, float* __restrict__ s,
                     float* __restrict__ d, int n) {
    int gt = blockIdx.x * blockDim.x + threadIdx.x;
    int warp = gt >> 5, lane = gt & 31;
    if (warp >= n * H) return;
    int node = warp / H, hh = warp % H;
    const float* row = h + (size_t)node * H * C + hh * C;
    float ss = 0.f, dd = 0.f;
    for (int c = lane; c < C; c += 32) {
        float v = row[c];
        ss += v * as_[hh * C + c];
        dd += v * ad_[hh * C + c];
    }
    #pragma unroll
    for (int o = 16; o; o >>= 1) {
        ss += __shfl_xor_sync(0xffffffffu, ss, o);
        dd += __shfl_xor_sync(0xffffffffu, dd, o);
    }
    if (lane == 0) { s[warp] = ss; d[warp] = dd; }
}

// ---------------- GAT aggregation: one block per dst node --------------------
template <int H, int C>
__global__ void k_gat_agg(const float* __restrict__ h, const float* __restrict__ s,
                          const float* __restrict__ dvals, const float* __restrict__ bias,
                          const int* __restrict__ rowptr, const int* __restrict__ csrsrc,
                          float* __restrict__ out) {
    constexpr int HC = H * C;
    int node = blockIdx.x;
    int tid = threadIdx.x;
    int warp = tid >> 5, lane = tid & 31;
    __shared__ float dv[H], mx[H], den[H];
    __shared__ int ssrc[32];
    __shared__ float wch[32 * H];
    int st = rowptr[node], en = rowptr[node + 1];
    if (tid < H) dv[tid] = dvals[node * H + tid];
    __syncthreads();
    // warp-per-head max & denominator (lanes stride over neighbors)
    if (warp < H) {
        float dvv = dv[warp];
        float m = -1e30f;
        for (int j = st + lane; j < en; j += 32) {
            float e = s[csrsrc[j] * H + warp] + dvv;
            e = e > 0.f ? e : NEG_SLOPE * e;
            m = fmaxf(m, e);
        }
        #pragma unroll
        for (int o = 16; o; o >>= 1) m = fmaxf(m, __shfl_xor_sync(0xffffffffu, m, o));
        float dn = 0.f;
        for (int j = st + lane; j < en; j += 32) {
            float e = s[csrsrc[j] * H + warp] + dvv;
            e = e > 0.f ? e : NEG_SLOPE * e;
            dn += expf(e - m);
        }
        #pragma unroll
        for (int o = 16; o; o >>= 1) dn += __shfl_xor_sync(0xffffffffu, dn, o);
        if (lane == 0) { mx[warp] = m; den[warp] = dn; }
    }
    float acc = 0.f;
    int head = tid / C;
    for (int base = st; base < en; base += 32) {
        int len = min(32, en - base);
        __syncthreads();  // protects ssrc/wch from previous chunk; mx/den visibility
        if (tid < len) ssrc[tid] = csrsrc[base + tid];
        __syncthreads();
        if (tid < len * H) {
            int j = tid / H, hh = tid - j * H;
            float e = s[ssrc[j] * H + hh] + dv[hh];
            e = e > 0.f ? e : NEG_SLOPE * e;
            wch[j * H + hh] = expf(e - mx[hh]);
        }
        __syncthreads();
        int j = 0;
        for (; j + 4 <= len; j += 4) {
            const float* p0 = h + (size_t)ssrc[j + 0] * HC;
            const float* p1 = h + (size_t)ssrc[j + 1] * HC;
            const float* p2 = h + (size_t)ssrc[j + 2] * HC;
            const float* p3 = h + (size_t)ssrc[j + 3] * HC;
            float w0 = wch[(j + 0) * H + head], w1 = wch[(j + 1) * H + head];
            float w2 = wch[(j + 2) * H + head], w3 = wch[(j + 3) * H + head];
            float v0 = p0[tid], v1 = p1[tid], v2 = p2[tid], v3 = p3[tid];
            acc += w0 * v0; acc += w1 * v1; acc += w2 * v2; acc += w3 * v3;
        }
        for (; j < len; j++)
            acc += wch[j * H + head] * h[(size_t)ssrc[j] * HC + tid];
    }
    float r = acc / den[head] + bias[tid];
    out[(size_t)node * HC + tid] = r > 0.f ? r : expm1f(r);
}

// ---------------- layer-3 aggregation (H=1, C=8): thread per node ------------
__global__ void k_gat_agg8(const float* __restrict__ h, const float* __restrict__ s,
                           const float* __restrict__ dvals, const float* __restrict__ bias,
                           const int* __restrict__ rowptr, const int* __restrict__ csrsrc,
                           float* __restrict__ out, int n) {
    int node = blockIdx.x * blockDim.x + threadIdx.x;
    if (node >= n) return;
    int st = rowptr[node], en = rowptr[node + 1];
    float dvv = dvals[node];
    float m = -1e30f;
    for (int j = st; j < en; j++) {
        float e = s[csrsrc[j]] + dvv;
        e = e > 0.f ? e : NEG_SLOPE * e;
        m = fmaxf(m, e);
    }
    float den = 0.f;
    float acc[8] = {};
    for (int j = st; j < en; j++) {
        int src = csrsrc[j];
        float e = s[src] + dvv;
        e = e > 0.f ? e : NEG_SLOPE * e;
        float w = expf(e - m);
        den += w;
        const float4* hp = (const float4*)(h + (size_t)src * 8);
        float4 v0 = hp[0], v1 = hp[1];
        acc[0] += w * v0.x; acc[1] += w * v0.y; acc[2] += w * v0.z; acc[3] += w * v0.w;
        acc[4] += w * v1.x; acc[5] += w * v1.y; acc[6] += w * v1.z; acc[7] += w * v1.w;
    }
    float inv = 1.f / den;
    #pragma unroll
    for (int c = 0; c < 8; c++) {
        float r = acc[c] * inv + bias[c];
        out[(size_t)node * 8 + c] = r > 0.f ? r : expm1f(r);
    }
}

// ---------------- final edge MLP ---------------------------------------------
__global__ void k_edge_mlp(const float* __restrict__ h, const int* __restrict__ src,
                           const int* __restrict__ dst, const float* __restrict__ ea,
                           const float* __restrict__ yr, const float* __restrict__ qt,
                           const float* __restrict__ w1, const float* __restrict__ b1,
                           const float* __restrict__ w2, const float* __restrict__ b2,
                           float* __restrict__ out, int e) {
    __shared__ float W1s[16 * 19];
    __shared__ float B1s[16];
    __shared__ float W2s[16];
    __shared__ float B2s;
    int tid = threadIdx.x;
    for (int i = tid; i < 304; i += blockDim.x) W1s[i] = w1[i];
    if (tid < 16) { B1s[tid] = b1[tid]; W2s[tid] = w2[tid]; }
    if (tid == 0) B2s = b2[0];
    __syncthreads();
    int i = blockIdx.x * blockDim.x + tid;
    if (i >= e) return;
    float z[19];
    int ss = src[i], dd = dst[i];
    const float4* hs = (const float4*)(h + (size_t)ss * 8);
    const float4* hd = (const float4*)(h + (size_t)dd * 8);
    float4 a0 = hs[0], a1 = hs[1], c0 = hd[0], c1 = hd[1];
    z[0] = a0.x; z[1] = a0.y; z[2] = a0.z; z[3] = a0.w;
    z[4] = a1.x; z[5] = a1.y; z[6] = a1.z; z[7] = a1.w;
    z[8] = c0.x; z[9] = c0.y; z[10] = c0.z; z[11] = c0.w;
    z[12] = c1.x; z[13] = c1.y; z[14] = c1.z; z[15] = c1.w;
    z[16] = ea[i]; z[17] = yr[i]; z[18] = qt[i];
    float o = B2s;
    #pragma unroll
    for (int r = 0; r < 16; r++) {
        float a = B1s[r];
        #pragma unroll
        for (int c = 0; c < 19; c++) a += W1s[r * 19 + c] * z[c];
        o += W2s[r] * fmaxf(a, 0.f);
    }
    out[i] = o;
}

// ---------------- launch -----------------------------------------------------
extern "C" void kernel_launch(void* const* d_in, const int* in_sizes, int n_in,
                              void* d_out, int out_size) {
    const float* x    = (const float*)d_in[0];
    const int*   ei   = (const int*)d_in[1];
    const float* ea   = (const float*)d_in[2];
    const float* yr   = (const float*)d_in[3];
    const float* qt   = (const float*)d_in[4];
    const float* W1   = (const float*)d_in[5];
    const float* a1s  = (const float*)d_in[6];
    const float* a1d  = (const float*)d_in[7];
    const float* b1   = (const float*)d_in[8];
    const float* W2   = (const float*)d_in[9];
    const float* a2s  = (const float*)d_in[10];
    const float* a2d  = (const float*)d_in[11];
    const float* b2   = (const float*)d_in[12];
    const float* W3   = (const float*)d_in[13];
    const float* a3s  = (const float*)d_in[14];
    const float* a3d  = (const float*)d_in[15];
    const float* b3   = (const float*)d_in[16];
    const float* fc1w = (const float*)d_in[17];
    const float* fc1b = (const float*)d_in[18];
    const float* fc2w = (const float*)d_in[19];
    const float* fc2b = (const float*)d_in[20];
    const int* srcp = ei;
    const int* dstp = ei + N_EDGES;
    float* out = (float*)d_out;

    float *h, *feat, *feat2, *sarr, *darr;
    int *cnt, *rowptr, *csrsrc, *part;
    cudaGetSymbolAddress((void**)&h,      g_h);
    cudaGetSymbolAddress((void**)&feat,   g_feat);
    cudaGetSymbolAddress((void**)&feat2,  g_feat2);
    cudaGetSymbolAddress((void**)&sarr,   g_s);
    cudaGetSymbolAddress((void**)&darr,   g_d);
    cudaGetSymbolAddress((void**)&cnt,    g_cnt);
    cudaGetSymbolAddress((void**)&rowptr, g_rowptr);
    cudaGetSymbolAddress((void**)&csrsrc, g_csrsrc);
    cudaGetSymbolAddress((void**)&part,   g_part);

    const int N = N_NODES, E = N_EDGES;
    const int NB = (N + 1023) / 1024;  // 49

    // CSR build (by destination, self-loops included)
    k_setone<<<(N + 255) / 256, 256>>>(cnt, N);
    k_count<<<(E + 255) / 256, 256>>>(dstp, cnt, E);
    k_blockscan<<<NB, 1024>>>(cnt, rowptr, part, N);
    k_scanpartials<<<1, 64>>>(part, rowptr, NB, N);
    k_addoff<<<(N + 255) / 256, 256>>>(rowptr, part, cnt, N);
    k_scatter<<<(E + N + 255) / 256, 256>>>(srcp, dstp, rowptr, cnt, csrsrc, E, N);

    // Layer 1: 128 -> 4x128
    {
        dim3 grid(512 / TBN, (N + TBM - 1) / TBM);
        k_sgemm<<<grid, 256>>>(N, 512, 128, x, W1, h);
        int warps = N * 4;
        k_sd<4, 128><<<(warps * 32 + 255) / 256, 256>>>(h, a1s, a1d, sarr, darr, N);
        k_gat_agg<4, 128><<<N, 512>>>(h, sarr, darr, b1, rowptr, csrsrc, feat);
    }
    // Layer 2: 512 -> 4x32
    {
        dim3 grid(128 / TBN, (N + TBM - 1) / TBM);
        k_sgemm<<<grid, 256>>>(N, 128, 512, feat, W2, h);
        int warps = N * 4;
        k_sd<4, 32><<<(warps * 32 + 255) / 256, 256>>>(h, a2s, a2d, sarr, darr, N);
        k_gat_agg<4, 32><<<N, 128>>>(h, sarr, darr, b2, rowptr, csrsrc, feat2);
    }
    // Layer 3: 128 -> 1x8
    {
        k_gemm8<<<(N + 255) / 256, 256>>>(feat2, W3, h, N);
        int warps = N * 1;
        k_sd<1, 8><<<(warps * 32 + 255) / 256, 256>>>(h, a3s, a3d, sarr, darr, N);
        k_gat_agg8<<<(N + 255) / 256, 256>>>(h, sarr, darr, b3, rowptr, csrsrc, feat, N);
    }
    // Edge MLP
    k_edge_mlp<<<(E + 255) / 256, 256>>>(feat, srcp, dstp, ea, yr, qt,
                                         fc1w, fc1b, fc2w, fc2b, out, E);
}